// round 9
// baseline (speedup 1.0000x reference)
#include <cuda_runtime.h>
#include <cuda_fp16.h>
#include <cstdint>

#define K_DIM 1024
#define M_DIM 2048
#define N_DIM 1024
#define NCHUNK 64

// Operands stored in m16n8k16 fragment order.
// g_Ahi/g_Alo: [chunk][mfrag 0..127][lane 0..31] -> uint4 {a0a1,a2a3,a4a5,a6a7}
// g_B:         [chunk][nfrag 0..127][lane 0..31] -> uint4 {whi0,whi1,wlo0,wlo1}
__device__ uint4 g_Ahi[(size_t)NCHUNK * 128 * 32];
__device__ uint4 g_Alo[(size_t)NCHUNK * 128 * 32];
__device__ uint4 g_Bfr[(size_t)NCHUNK * 128 * 32];

// ---------------------------------------------------------------------------
// Fused prep: blocks [0,512) do X, [512,768) do W.
// Computes hi/lo fp16 split, then shuffles through smem into fragment layout.
// ---------------------------------------------------------------------------
__global__ void prep_kernel(const float* __restrict__ X,
                            const float* __restrict__ W,
                            const float* __restrict__ vmap,
                            const float* __restrict__ wmap) {
    __shared__ float s_lut[256];
    __shared__ unsigned sHi[256][9];
    __shared__ unsigned sLo[256][9];

    const int tid = threadIdx.x;
    const bool isX = blockIdx.x < 512;
    s_lut[tid] = isX ? vmap[tid] : wmap[tid];
    __syncthreads();

    unsigned hi[8], lo[8];
    if (isX) {
        const int b = blockIdx.x;
        const int r = b >> 3, m0b = (b & 7) * 256;
        const int m = m0b + tid;
        const float* src = X + (size_t)m * K_DIM + r * 16;
        float xs[16];
        ((float4*)xs)[0] = ((const float4*)src)[0];
        ((float4*)xs)[1] = ((const float4*)src)[1];
        ((float4*)xs)[2] = ((const float4*)src)[2];
        ((float4*)xs)[3] = ((const float4*)src)[3];
#pragma unroll
        for (int jj = 0; jj < 8; jj++) {
            unsigned short h[2], l[2];
#pragma unroll
            for (int e = 0; e < 2; e++) {
                int j = 2 * jj + e;
                float xv = xs[j];
                int idx = (int)(xv + 8.0f);
                idx = idx < 0 ? 0 : (idx > 15 ? 15 : idx);
                float xc = (xv + s_lut[j * 16 + idx]) * 0.0625f;
                __half hh = __float2half_rn(xc);
                __half ll = __float2half_rn(xc - __half2float(hh));
                h[e] = __half_as_ushort(hh);
                l[e] = __half_as_ushort(ll);
            }
            hi[jj] = h[0] | ((unsigned)h[1] << 16);
            lo[jj] = l[0] | ((unsigned)l[1] << 16);
        }
#pragma unroll
        for (int jj = 0; jj < 8; jj++) { sHi[tid][jj] = hi[jj]; sLo[tid][jj] = lo[jj]; }
        __syncthreads();

#pragma unroll
        for (int ss = 0; ss < 2; ss++) {
            int s = tid + 256 * ss;
            int f = s >> 5, l = s & 31, g = l >> 2, tq = l & 3;
            int r0 = f * 16 + g, r1 = r0 + 8;
            uint4 H = make_uint4(sHi[r0][tq], sHi[r1][tq], sHi[r0][tq + 4], sHi[r1][tq + 4]);
            uint4 L = make_uint4(sLo[r0][tq], sLo[r1][tq], sLo[r0][tq + 4], sLo[r1][tq + 4]);
            size_t gi = ((size_t)r * 128 + (m0b >> 4) + f) * 32 + l;
            g_Ahi[gi] = H;
            g_Alo[gi] = L;
        }
    } else {
        const int b = blockIdx.x - 512;
        const int r = b >> 2, n0b = (b & 3) * 256;
        const int n = n0b + tid;
#pragma unroll
        for (int jj = 0; jj < 8; jj++) {
            unsigned short h[2], l[2];
#pragma unroll
            for (int e = 0; e < 2; e++) {
                int j = 2 * jj + e;
                float w = W[(size_t)(16 * r + j) * N_DIM + n];
                int idx = (int)(w + 8.0f);
                idx = idx < 0 ? 0 : (idx > 15 ? 15 : idx);
                float wc = w + s_lut[j * 16 + idx];
                __half hh = __float2half_rn(wc);
                __half ll = __float2half_rn(wc - __half2float(hh));
                h[e] = __half_as_ushort(hh);
                l[e] = __half_as_ushort(ll);
            }
            hi[jj] = h[0] | ((unsigned)h[1] << 16);
            lo[jj] = l[0] | ((unsigned)l[1] << 16);
        }
#pragma unroll
        for (int jj = 0; jj < 8; jj++) { sHi[tid][jj] = hi[jj]; sLo[tid][jj] = lo[jj]; }
        __syncthreads();

#pragma unroll
        for (int ss = 0; ss < 4; ss++) {
            int s = tid + 256 * ss;
            int f = s >> 5, l = s & 31, g = l >> 2, tq = l & 3;
            int nl = f * 8 + g;
            uint4 V = make_uint4(sHi[nl][tq], sHi[nl][tq + 4], sLo[nl][tq], sLo[nl][tq + 4]);
            g_Bfr[((size_t)r * 128 + (n0b >> 3) + f) * 32 + l] = V;
        }
    }
}

// ---------------------------------------------------------------------------
#define MMA_INIT(C, A, B0, B1, Z)                                              \
    asm("mma.sync.aligned.m16n8k16.row.col.f32.f16.f16.f32 "                   \
        "{%0,%1,%2,%3}, {%4,%5,%6,%7}, {%8,%9}, {%10,%10,%10,%10};"            \
        : "=f"((C)[0]), "=f"((C)[1]), "=f"((C)[2]), "=f"((C)[3])               \
        : "r"((A).x), "r"((A).y), "r"((A).z), "r"((A).w), "r"(B0), "r"(B1),    \
          "f"(Z))

// fp16-accumulate MMA: D/C are 2 packed-half2 regs
#define MMAH_INIT(C, A, B0, B1, Z)                                             \
    asm("mma.sync.aligned.m16n8k16.row.col.f16.f16.f16.f16 "                   \
        "{%0,%1}, {%2,%3,%4,%5}, {%6,%7}, {%8,%8};"                            \
        : "=r"((C)[0]), "=r"((C)[1])                                           \
        : "r"((A).x), "r"((A).y), "r"((A).z), "r"((A).w), "r"(B0), "r"(B1),    \
          "r"(Z))

#define MMAH_ACC(C, A, B0, B1)                                                 \
    asm("mma.sync.aligned.m16n8k16.row.col.f16.f16.f16.f16 "                   \
        "{%0,%1}, {%2,%3,%4,%5}, {%6,%7}, {%0,%1};"                            \
        : "+r"((C)[0]), "+r"((C)[1])                                           \
        : "r"((A).x), "r"((A).y), "r"((A).z), "r"((A).w), "r"(B0), "r"(B1))

// ---------------------------------------------------------------------------
// Main: no smem, no barriers. Big term hi*whi in f32-accum MMA; small terms
// hi*wlo + lo*whi chained in ONE f16-accum pair (2x rate). Per-chunk RNE.
// CTA tile 128m x 64n, 8 warps 4(m) x 2(n). grid (16,16), 2 CTA/SM.
// ---------------------------------------------------------------------------
__global__ void __launch_bounds__(256, 2)
opu_main_kernel(float* __restrict__ out) {
    const int t = threadIdx.x, wid = t >> 5, lane = t & 31;
    const int m0 = blockIdx.x * 128, n0 = blockIdx.y * 64;
    const int wm = (wid >> 1) * 32, wn = (wid & 1) * 32;

    const int mf = (m0 + wm) >> 4;
    const int nf = (n0 + wn) >> 3;

    const uint4* pA0 = g_Ahi + (size_t)mf * 32 + lane;
    const uint4* pA1 = g_Alo + (size_t)mf * 32 + lane;
    const uint4* pB  = g_Bfr + (size_t)nf * 32 + lane;
    const size_t CSTR = 128 * 32;

    unsigned su[2][4][4];
#pragma unroll
    for (int i = 0; i < 2; i++)
#pragma unroll
        for (int j = 0; j < 4; j++)
#pragma unroll
            for (int e = 0; e < 4; e++) su[i][j][e] = 0u;

    const float FZ = 0.0f;
    const unsigned HZ = 0u;
    const float MAGIC = 12582912.0f;   // 1.5*2^23

    uint4 AH[2][2], AL[2][2], BF[2][4];

#define LOAD_CHUNK(buf, r)                                                     \
    do {                                                                       \
        const size_t o = (size_t)(r) * CSTR;                                   \
        AH[buf][0] = pA0[o];        AH[buf][1] = pA0[o + 32];                  \
        AL[buf][0] = pA1[o];        AL[buf][1] = pA1[o + 32];                  \
        BF[buf][0] = pB[o];         BF[buf][1] = pB[o + 32];                   \
        BF[buf][2] = pB[o + 64];    BF[buf][3] = pB[o + 96];                   \
    } while (0)

#define COMPUTE_CHUNK(buf)                                                     \
    do {                                                                       \
        _Pragma("unroll")                                                      \
        for (int i = 0; i < 2; i++) {                                          \
            _Pragma("unroll")                                                  \
            for (int jp = 0; jp < 2; jp++) {                                   \
                float a0[4], a1[4];                                            \
                unsigned c0[2], c1[2];                                         \
                const uint4 b0 = BF[buf][2 * jp], b1 = BF[buf][2 * jp + 1];    \
                MMA_INIT(a0, AH[buf][i], b0.x, b0.y, FZ);   /* hi*whi f32 */   \
                MMA_INIT(a1, AH[buf][i], b1.x, b1.y, FZ);                      \
                MMAH_INIT(c0, AH[buf][i], b0.z, b0.w, HZ);  /* hi*wlo f16 */   \
                MMAH_INIT(c1, AH[buf][i], b1.z, b1.w, HZ);                     \
                MMAH_ACC(c0, AL[buf][i], b0.x, b0.y);       /* + lo*whi */     \
                MMAH_ACC(c1, AL[buf][i], b1.x, b1.y);                          \
                float2 f0a = __half22float2(*(__half2*)&c0[0]);                \
                float2 f0b = __half22float2(*(__half2*)&c0[1]);                \
                float2 f1a = __half22float2(*(__half2*)&c1[0]);                \
                float2 f1b = __half22float2(*(__half2*)&c1[1]);                \
                su[i][2 * jp][0]     += __float_as_uint((a0[0] + f0a.x) + MAGIC); \
                su[i][2 * jp][1]     += __float_as_uint((a0[1] + f0a.y) + MAGIC); \
                su[i][2 * jp][2]     += __float_as_uint((a0[2] + f0b.x) + MAGIC); \
                su[i][2 * jp][3]     += __float_as_uint((a0[3] + f0b.y) + MAGIC); \
                su[i][2 * jp + 1][0] += __float_as_uint((a1[0] + f1a.x) + MAGIC); \
                su[i][2 * jp + 1][1] += __float_as_uint((a1[1] + f1a.y) + MAGIC); \
                su[i][2 * jp + 1][2] += __float_as_uint((a1[2] + f1b.x) + MAGIC); \
                su[i][2 * jp + 1][3] += __float_as_uint((a1[3] + f1b.y) + MAGIC); \
            }                                                                  \
        }                                                                      \
    } while (0)

    LOAD_CHUNK(0, 0);
    for (int r = 0; r < NCHUNK; r += 2) {
        LOAD_CHUNK(1, r + 1);
        COMPUTE_CHUNK(0);
        int r2 = (r + 2 < NCHUNK) ? r + 2 : NCHUNK - 1;
        LOAD_CHUNK(0, r2);
        COMPUTE_CHUNK(1);
    }

    // out = 16 * (su - 64*0x4B400000 mod 2^32)
    const unsigned BIAS64 = 0xD0000000u;
    const int g = lane >> 2, tg = lane & 3;
#pragma unroll
    for (int i = 0; i < 2; i++)
#pragma unroll
        for (int h = 0; h < 2; h++) {
            int row = m0 + wm + 16 * i + 8 * h + g;
            float* orow = out + (size_t)row * N_DIM + n0 + wn + 2 * tg;
#pragma unroll
            for (int j = 0; j < 4; j++) {
                float2 o;
                o.x = 16.0f * (float)(int)(su[i][j][2 * h + 0] - BIAS64);
                o.y = 16.0f * (float)(int)(su[i][j][2 * h + 1] - BIAS64);
                *(float2*)(orow + 8 * j) = o;
            }
        }
#undef LOAD_CHUNK
#undef COMPUTE_CHUNK
}

// ---------------------------------------------------------------------------
extern "C" void kernel_launch(void* const* d_in, const int* in_sizes, int n_in,
                              void* d_out, int out_size) {
    const float* X    = (const float*)d_in[0];  // (2,1024,1024)
    const float* W    = (const float*)d_in[1];  // (1024,1024)
    const float* vmap = (const float*)d_in[2];  // (16,16)
    const float* wmap = (const float*)d_in[3];  // (16,16)
    float* out = (float*)d_out;                 // (2,1024,1024)

    prep_kernel<<<768, 256>>>(X, W, vmap, wmap);
    opu_main_kernel<<<dim3(16, 16), 256>>>(out);
}